// round 4
// baseline (speedup 1.0000x reference)
#include <cuda_runtime.h>
#include <math.h>

// QSP expectation Re(<0|U|0>) = f(cos x); f has even parity, degree 54 in c
// => f = sum_{j=0}^{27} d_j T_j(y), y = cos(2x).
// Further split: f(y) = G(u) + y*H(u), u = 2y^2-1 = cos(4x), with
//   g_m = d_{2m}                         (T_{2m}(y) = T_m(u))
//   h_0 = sum_m (-1)^m d_{2m+1},  h_k = 2*sum_{m>=k} (-1)^(m-k) d_{2m+1}
// (from T_{2m+1}(y) = y*Q_m(u), Q_m = (-1)^m T_0 + 2 sum_{k=1..m} (-1)^(m-k) T_k).
// Fused kernel: per-block prologue computes d_j at 28 Chebyshev nodes via
// parallel SU(2) chunk products + exact-angle DCT, transforms to g/h, then
// evaluates 4 elems/thread with two 13-step packed-f32x2 Clenshaw chains.

#define NSTEPS 54
#define NPH    55
#define NNODE  28
#define NCHUNK 9
#define CSTEP  6
#define NHALF  14          // g_0..g_13, h_0..h_13

typedef unsigned long long u64;

__device__ __forceinline__ u64 pack2(float lo, float hi) {
    u64 r; asm("mov.b64 %0, {%1, %2};" : "=l"(r) : "f"(lo), "f"(hi)); return r;
}
__device__ __forceinline__ void unpack2(u64 v, float& lo, float& hi) {
    asm("mov.b64 {%0, %1}, %2;" : "=f"(lo), "=f"(hi) : "l"(v));
}
__device__ __forceinline__ u64 fma2(u64 a, u64 b, u64 c) {
    u64 d; asm("fma.rn.f32x2 %0, %1, %2, %3;" : "=l"(d) : "l"(a), "l"(b), "l"(c)); return d;
}
__device__ __forceinline__ u64 add2(u64 a, u64 b) {
    u64 d; asm("add.rn.f32x2 %0, %1, %2;" : "=l"(d) : "l"(a), "l"(b)); return d;
}

#define SU2_COMPOSE(a_r,a_i,b_r,b_i, alr,ali,ber,bei) do {                   \
    float nar = a_r*alr - a_i*ali - b_r*ber - b_i*bei;                       \
    float nai = a_r*ali + a_i*alr + b_r*bei - b_i*ber;                       \
    float nbr = a_r*ber - a_i*bei + b_r*alr + b_i*ali;                       \
    float nbi = a_r*bei + a_i*ber + b_i*alr - b_r*ali;                       \
    a_r = nar; a_i = nai; b_r = nbr; b_i = nbi;                              \
} while (0)

__global__ void __launch_bounds__(256) qsp_fused(
    const float4* __restrict__ x4,
    const float*  __restrict__ p,
    const float4* __restrict__ a4,
    const float*  __restrict__ bias,
    float4* __restrict__ out4,
    int n4)
{
    __shared__ float  ph[NPH];
    __shared__ float4 chunk[NNODE * NCHUNK];
    __shared__ float  fsh[NNODE];
    __shared__ float  dsh[NNODE];
    __shared__ float2 gsh[NHALF];
    __shared__ float2 hsh[NHALF];
    const float PI = 3.14159265358979323846f;
    int tid = threadIdx.x;

    if (tid < NPH) ph[tid] = p[tid];
    __syncthreads();

    // Phase 1: 252 threads, each a 6-step SU(2) partial product at node m.
    if (tid < NNODE * NCHUNK) {
        int m = tid / NCHUNK;
        int j = tid % NCHUNK;
        float th = PI * ((float)m + 0.5f) / 56.0f;    // y_m = cos(2*th)
        float cm, sm;
        sincosf(th, &sm, &cm);
        float a_r = 1.f, a_i = 0.f, b_r = 0.f, b_i = 0.f;
        #pragma unroll
        for (int s = 0; s < CSTEP; s++) {
            int k = 1 + j * CSTEP + s;
            float er, ei;
            __sincosf(ph[k], &ei, &er);
            float alr = cm * er, ali = cm * ei;
            float ber = sm * ei, bei = sm * er;
            SU2_COMPOSE(a_r, a_i, b_r, b_i, alr, ali, ber, bei);
        }
        chunk[tid] = make_float4(a_r, a_i, b_r, b_i);
    }
    __syncthreads();

    // Phase 2: per-node composition of 9 chunks.
    if (tid < NNODE) {
        float4 C = chunk[tid * NCHUNK];
        float a_r = C.x, a_i = C.y, b_r = C.z, b_i = C.w;
        #pragma unroll
        for (int j = 1; j < NCHUNK; j++) {
            float4 Mv = chunk[tid * NCHUNK + j];
            SU2_COMPOSE(a_r, a_i, b_r, b_i, Mv.x, Mv.y, Mv.z, Mv.w);
        }
        float c0, s0;
        sincosf(ph[0], &s0, &c0);
        fsh[tid] = c0 * a_r - s0 * a_i;
    }
    __syncthreads();

    // Phase 3: 28-point DCT -> d_j (exact integer angle reduction mod 112).
    if (tid < NNODE) {
        int j = tid;
        float s = 0.f;
        #pragma unroll 1
        for (int m = 0; m < NNODE; m++) {
            int r = (j * (2 * m + 1)) % 112;
            float ang = (PI / 56.0f) * (float)r - PI;
            s = fmaf(fsh[m], -__cosf(ang), s);
        }
        s *= 2.0f / (float)NNODE;
        if (j == 0) s *= 0.5f;
        dsh[j] = s;
    }
    __syncthreads();

    // Phase 4: split into even part g and odd part h (exact integer weights).
    if (tid < NHALF) {
        float g = dsh[2 * tid];
        gsh[tid] = make_float2(g, g);
        float h = 0.f, sign = 1.f;
        #pragma unroll 1
        for (int m = tid; m < NHALF; m++) {
            h = fmaf(sign, dsh[2 * m + 1], h);
            sign = -sign;
        }
        if (tid > 0) h *= 2.0f;
        hsh[tid] = make_float2(h, h);
    }
    __syncthreads();

    // Eval: 4 elements/thread (2 packed pairs), two 13-step Clenshaw chains
    // (G in u, H in u), then f = G + y*H; out = alpha*f + bias. All f32x2.
    int i = blockIdx.x * blockDim.x + tid;
    if (i >= n4) return;

    float4 xv = x4[i];
    float4 av = a4[i];
    float  b0 = __ldg(bias);

    float y0 = __cosf(2.0f * xv.x), y1 = __cosf(2.0f * xv.y);
    float y2 = __cosf(2.0f * xv.z), y3 = __cosf(2.0f * xv.w);

    u64 neg1 = pack2(-1.f, -1.f);
    u64 yP = pack2(y0, y1), yQ = pack2(y2, y3);
    u64 dyP = add2(yP, yP), dyQ = add2(yQ, yQ);
    u64 uP = fma2(dyP, yP, neg1);          // u = 2y^2 - 1
    u64 uQ = fma2(dyQ, yQ, neg1);
    u64 tuP = add2(uP, uP), tuQ = add2(uQ, uQ);

    u64 gb1P = 0, gb2P = 0, hb1P = 0, hb2P = 0;
    u64 gb1Q = 0, gb2Q = 0, hb1Q = 0, hb2Q = 0;

    #pragma unroll
    for (int k = NHALF - 1; k >= 1; k--) {
        float2 gt = gsh[k];
        float2 ht = hsh[k];
        u64 gk, hk;
        asm("mov.b64 %0, {%1, %2};" : "=l"(gk) : "f"(gt.x), "f"(gt.y));
        asm("mov.b64 %0, {%1, %2};" : "=l"(hk) : "f"(ht.x), "f"(ht.y));
        u64 ugP = fma2(neg1, gb2P, gk);
        u64 uhP = fma2(neg1, hb2P, hk);
        u64 ugQ = fma2(neg1, gb2Q, gk);
        u64 uhQ = fma2(neg1, hb2Q, hk);
        u64 ngP = fma2(tuP, gb1P, ugP);
        u64 nhP = fma2(tuP, hb1P, uhP);
        u64 ngQ = fma2(tuQ, gb1Q, ugQ);
        u64 nhQ = fma2(tuQ, hb1Q, uhQ);
        gb2P = gb1P; gb1P = ngP;  hb2P = hb1P; hb1P = nhP;
        gb2Q = gb1Q; gb1Q = ngQ;  hb2Q = hb1Q; hb1Q = nhQ;
    }

    float2 g0t = gsh[0], h0t = hsh[0];
    u64 g0k, h0k;
    asm("mov.b64 %0, {%1, %2};" : "=l"(g0k) : "f"(g0t.x), "f"(g0t.y));
    asm("mov.b64 %0, {%1, %2};" : "=l"(h0k) : "f"(h0t.x), "f"(h0t.y));

    u64 GP = fma2(uP, gb1P, fma2(neg1, gb2P, g0k));
    u64 HP = fma2(uP, hb1P, fma2(neg1, hb2P, h0k));
    u64 GQ = fma2(uQ, gb1Q, fma2(neg1, gb2Q, g0k));
    u64 HQ = fma2(uQ, hb1Q, fma2(neg1, hb2Q, h0k));

    u64 fP = fma2(yP, HP, GP);             // f = G + y*H
    u64 fQ = fma2(yQ, HQ, GQ);

    u64 aP = pack2(av.x, av.y), aQ = pack2(av.z, av.w);
    u64 bP = pack2(b0, b0);
    u64 oP = fma2(aP, fP, bP);
    u64 oQ = fma2(aQ, fQ, bP);

    float4 o;
    unpack2(oP, o.x, o.y);
    unpack2(oQ, o.z, o.w);
    out4[i] = o;
}

extern "C" void kernel_launch(void* const* d_in, const int* in_sizes, int n_in,
                              void* d_out, int out_size) {
    const float* x    = (const float*)d_in[0];
    const float* p    = (const float*)d_in[1];
    const float* al   = (const float*)d_in[2];
    const float* bias = (const float*)d_in[3];

    int n4 = out_size / 4;                       // 131072
    int threads = 256;
    int blocks = (n4 + threads - 1) / threads;   // 512 blocks, 4 elem/thread
    qsp_fused<<<blocks, threads>>>((const float4*)x, p, (const float4*)al, bias,
                                   (float4*)d_out, n4);
}

// round 7
// speedup vs baseline: 1.1476x; 1.1476x over previous
#include <cuda_runtime.h>
#include <math.h>

// QSP expectation Re(<0|U|0>) = f(cos x); f even parity, degree 54 in c
// => f = sum_{j=0}^{27} d_j T_j(y), y = cos(2x)
// => f(y) = G(u) + y*H(u), u = 2y^2-1 = cos(4x),
//    g_m = d_{2m};  h_0 = sum_m (-1)^m d_{2m+1}, h_k = 2 sum_{m>=k} (-1)^(m-k) d_{2m+1}.
// Fused kernel. Prologue (per block, redundant): f at 28 Chebyshev nodes via
// parallel SU(2) chunk products, 28-pt DCT (exact integer angle reduction),
// even/odd split. Eval: coefficients REGISTER-RESIDENT, pure scalar Clenshaw,
// 4 elems/thread x 2 polys = 8 independent 13-step chains, no LDS in loop.

#define NSTEPS 54
#define NPH    55
#define NNODE  28
#define NCHUNK 9
#define CSTEP  6
#define NHALF  14

#define SU2_COMPOSE(a_r,a_i,b_r,b_i, alr,ali,ber,bei) do {                   \
    float nar = a_r*alr - a_i*ali - b_r*ber - b_i*bei;                       \
    float nai = a_r*ali + a_i*alr + b_r*bei - b_i*ber;                       \
    float nbr = a_r*ber - a_i*bei + b_r*alr + b_i*ali;                       \
    float nbi = a_r*bei + a_i*ber + b_i*alr - b_r*ali;                       \
    a_r = nar; a_i = nai; b_r = nbr; b_i = nbi;                              \
} while (0)

__global__ void __launch_bounds__(256) qsp_fused(
    const float4* __restrict__ x4,
    const float*  __restrict__ p,
    const float4* __restrict__ a4,
    const float*  __restrict__ bias,
    float4* __restrict__ out4,
    int n4)
{
    __shared__ float  ph[NPH];
    __shared__ float4 chunk[NNODE * NCHUNK];
    __shared__ float  fsh[NNODE];
    __shared__ float  dsh[NNODE];
    __shared__ float  gsh[NHALF];
    __shared__ float  hsh[NHALF];
    const float PI = 3.14159265358979323846f;
    int tid = threadIdx.x;

    if (tid < NPH) ph[tid] = p[tid];
    __syncthreads();

    // Phase 1: 252 threads, each a 6-step SU(2) partial product at node m.
    if (tid < NNODE * NCHUNK) {
        int m = tid / NCHUNK;
        int j = tid % NCHUNK;
        float th = PI * ((float)m + 0.5f) / 56.0f;     // y_m = cos(2*th)
        float cm, sm;
        sincosf(th, &sm, &cm);
        // prefetch my 6 phases to break LDS out of the serial chain
        float myph[CSTEP];
        #pragma unroll
        for (int s = 0; s < CSTEP; s++) myph[s] = ph[1 + j * CSTEP + s];
        float a_r = 1.f, a_i = 0.f, b_r = 0.f, b_i = 0.f;
        #pragma unroll
        for (int s = 0; s < CSTEP; s++) {
            float er, ei;
            __sincosf(myph[s], &ei, &er);
            float alr = cm * er, ali = cm * ei;        // alpha = c*e
            float ber = sm * ei, bei = sm * er;        // beta  = i*s*conj(e)
            SU2_COMPOSE(a_r, a_i, b_r, b_i, alr, ali, ber, bei);
        }
        chunk[tid] = make_float4(a_r, a_i, b_r, b_i);
    }
    __syncthreads();

    // Phase 2: per-node ordered composition of 9 chunks (prefetched to regs).
    if (tid < NNODE) {
        float4 Mv[NCHUNK];
        #pragma unroll
        for (int j = 0; j < NCHUNK; j++) Mv[j] = chunk[tid * NCHUNK + j];
        float a_r = Mv[0].x, a_i = Mv[0].y, b_r = Mv[0].z, b_i = Mv[0].w;
        #pragma unroll
        for (int j = 1; j < NCHUNK; j++)
            SU2_COMPOSE(a_r, a_i, b_r, b_i, Mv[j].x, Mv[j].y, Mv[j].z, Mv[j].w);
        float c0, s0;
        sincosf(ph[0], &s0, &c0);
        fsh[tid] = c0 * a_r - s0 * a_i;                // f(theta_m)
    }
    __syncthreads();

    // Phase 3: 28-point DCT -> d_j, exact integer angle reduction mod 112.
    if (tid < NNODE) {
        int j = tid;
        float s0a = 0.f, s1a = 0.f;
        #pragma unroll
        for (int m = 0; m < NNODE; m += 2) {
            int r0 = (j * (2 * m + 1)) % 112;
            int r1 = (j * (2 * m + 3)) % 112;
            float a0 = (PI / 56.0f) * (float)r0 - PI;
            float a1 = (PI / 56.0f) * (float)r1 - PI;
            s0a = fmaf(fsh[m],     -__cosf(a0), s0a);  // cos(pi r/56) = -cos(ang)
            s1a = fmaf(fsh[m + 1], -__cosf(a1), s1a);
        }
        float s = (s0a + s1a) * (2.0f / (float)NNODE);
        if (j == 0) s *= 0.5f;
        dsh[j] = s;
    }
    __syncthreads();

    // Phase 4: even/odd split with exact integer weights.
    if (tid < NHALF) {
        gsh[tid] = dsh[2 * tid];
        float h = 0.f, sign = 1.f;
        #pragma unroll 1
        for (int m = tid; m < NHALF; m++) {
            h = fmaf(sign, dsh[2 * m + 1], h);
            sign = -sign;
        }
        if (tid > 0) h *= 2.0f;
        hsh[tid] = h;
    }
    __syncthreads();

    // Pull all 28 coefficients into registers (one-time broadcast LDS).
    float g[NHALF], h[NHALF];
    #pragma unroll
    for (int k = 0; k < NHALF; k++) { g[k] = gsh[k]; h[k] = hsh[k]; }

    int i = blockIdx.x * blockDim.x + tid;
    if (i >= n4) return;

    float4 xv = x4[i];
    float4 av = a4[i];
    float  b0 = __ldg(bias);

    float y[4], u[4], tu[4];
    y[0] = __cosf(2.0f * xv.x); y[1] = __cosf(2.0f * xv.y);
    y[2] = __cosf(2.0f * xv.z); y[3] = __cosf(2.0f * xv.w);
    #pragma unroll
    for (int e = 0; e < 4; e++) {
        u[e]  = fmaf(2.0f * y[e], y[e], -1.0f);        // u = 2y^2-1
        tu[e] = 2.0f * u[e];
    }

    float gb1[4] = {0,0,0,0}, gb2[4] = {0,0,0,0};
    float hb1[4] = {0,0,0,0}, hb2[4] = {0,0,0,0};

    // Clenshaw in u: 8 independent 13-step chains, all operands in registers.
    #pragma unroll
    for (int k = NHALF - 1; k >= 1; k--) {
        float gk = g[k], hk = h[k];
        #pragma unroll
        for (int e = 0; e < 4; e++) {
            float ng = fmaf(tu[e], gb1[e], gk - gb2[e]);
            float nh = fmaf(tu[e], hb1[e], hk - hb2[e]);
            gb2[e] = gb1[e]; gb1[e] = ng;
            hb2[e] = hb1[e]; hb1[e] = nh;
        }
    }

    float4 o;
    float f[4];
    #pragma unroll
    for (int e = 0; e < 4; e++) {
        float G = fmaf(u[e], gb1[e], g[0] - gb2[e]);
        float H = fmaf(u[e], hb1[e], h[0] - hb2[e]);
        f[e] = fmaf(y[e], H, G);                       // f = G + y*H
    }
    o.x = fmaf(av.x, f[0], b0);
    o.y = fmaf(av.y, f[1], b0);
    o.z = fmaf(av.z, f[2], b0);
    o.w = fmaf(av.w, f[3], b0);
    out4[i] = o;
}

extern "C" void kernel_launch(void* const* d_in, const int* in_sizes, int n_in,
                              void* d_out, int out_size) {
    const float* x    = (const float*)d_in[0];
    const float* p    = (const float*)d_in[1];
    const float* al   = (const float*)d_in[2];
    const float* bias = (const float*)d_in[3];

    int n4 = out_size / 4;                        // 131072
    int threads = 256;
    int blocks = (n4 + threads - 1) / threads;    // 512 blocks, 4 elem/thread
    qsp_fused<<<blocks, threads>>>((const float4*)x, p, (const float4*)al, bias,
                                   (float4*)d_out, n4);
}

// round 11
// speedup vs baseline: 1.2054x; 1.0504x over previous
#include <cuda_runtime.h>
#include <math.h>

// QSP expectation Re(<0|U|0>) = f(cos x); f even parity, degree 54 in c
// => f = sum_{j=0}^{27} d_j T_j(y), y = cos(2x)
// => f(y) = G(u) + y*H(u), u = 2y^2-1 = cos(4x),
//    g_m = d_{2m};  h_0 = sum_m (-1)^m d_{2m+1}, h_k = 2 sum_{m>=k} (-1)^(m-k) d_{2m+1}.
// Fused kernel, instruction-minimized:
//  - 296 blocks x 448 threads (exactly 2 CTAs/SM) -> 296 redundant prologues, not 512
//  - prologue: __sincosf nodes, chunk init-from-first, DCT spread over 112 threads
//  - eval: packed fp32x2 FMA, 4 chains x 13 steps, coeffs as float2 in shared

#define NSTEPS 54
#define NPH    55
#define NNODE  28
#define NCHUNK 9
#define CSTEP  6
#define NHALF  14

typedef unsigned long long u64;

__device__ __forceinline__ u64 pack2(float lo, float hi) {
    u64 r; asm("mov.b64 %0, {%1, %2};" : "=l"(r) : "f"(lo), "f"(hi)); return r;
}
__device__ __forceinline__ void unpack2(u64 v, float& lo, float& hi) {
    asm("mov.b64 {%0, %1}, %2;" : "=f"(lo), "=f"(hi) : "l"(v));
}
__device__ __forceinline__ u64 fma2(u64 a, u64 b, u64 c) {
    u64 d; asm("fma.rn.f32x2 %0, %1, %2, %3;" : "=l"(d) : "l"(a), "l"(b), "l"(c)); return d;
}
__device__ __forceinline__ u64 add2(u64 a, u64 b) {
    u64 d; asm("add.rn.f32x2 %0, %1, %2;" : "=l"(d) : "l"(a), "l"(b)); return d;
}

#define SU2_COMPOSE(a_r,a_i,b_r,b_i, alr,ali,ber,bei) do {                   \
    float nar = a_r*alr - a_i*ali - b_r*ber - b_i*bei;                       \
    float nai = a_r*ali + a_i*alr + b_r*bei - b_i*ber;                       \
    float nbr = a_r*ber - a_i*bei + b_r*alr + b_i*ali;                       \
    float nbi = a_r*bei + a_i*ber + b_i*alr - b_r*ali;                       \
    a_r = nar; a_i = nai; b_r = nbr; b_i = nbi;                              \
} while (0)

__global__ void __launch_bounds__(448) qsp_fused(
    const float4* __restrict__ x4,
    const float*  __restrict__ p,
    const float4* __restrict__ a4,
    const float*  __restrict__ bias,
    float4* __restrict__ out4,
    int n4)
{
    __shared__ float  ph[NPH];
    __shared__ float4 chunk[NNODE * NCHUNK];
    __shared__ float  fsh[NNODE];
    __shared__ float  psum[NNODE * 4];
    __shared__ float  dsh[NNODE];
    __shared__ float2 gsh[NHALF];
    __shared__ float2 hsh[NHALF];
    const float PI = 3.14159265358979323846f;
    int tid = threadIdx.x;

    if (tid < NPH) ph[tid] = p[tid];
    __syncthreads();

    // Phase 1: 252 threads, each a 6-step SU(2) partial product at node m.
    // Initialize from the first matrix (5 composes, not 6). Cheap MUFU node.
    if (tid < NNODE * NCHUNK) {
        int m = tid / NCHUNK;
        int j = tid % NCHUNK;
        float th = PI * ((float)m + 0.5f) / 56.0f;     // y_m = cos(2*th)
        float cm, sm;
        __sincosf(th, &sm, &cm);                       // node err ~1e-6, fine
        float myph[CSTEP];
        #pragma unroll
        for (int s = 0; s < CSTEP; s++) myph[s] = ph[1 + j * CSTEP + s];
        float er, ei;
        __sincosf(myph[0], &ei, &er);
        float a_r = cm * er, a_i = cm * ei;            // C = M_first
        float b_r = sm * ei, b_i = sm * er;
        #pragma unroll
        for (int s = 1; s < CSTEP; s++) {
            __sincosf(myph[s], &ei, &er);
            float alr = cm * er, ali = cm * ei;        // alpha = c*e
            float ber = sm * ei, bei = sm * er;        // beta  = i*s*conj(e)
            SU2_COMPOSE(a_r, a_i, b_r, b_i, alr, ali, ber, bei);
        }
        chunk[tid] = make_float4(a_r, a_i, b_r, b_i);
    }
    __syncthreads();

    // Phase 2: per-node ordered composition of 9 chunks.
    if (tid < NNODE) {
        float4 Mv[NCHUNK];
        #pragma unroll
        for (int j = 0; j < NCHUNK; j++) Mv[j] = chunk[tid * NCHUNK + j];
        float a_r = Mv[0].x, a_i = Mv[0].y, b_r = Mv[0].z, b_i = Mv[0].w;
        #pragma unroll
        for (int j = 1; j < NCHUNK; j++)
            SU2_COMPOSE(a_r, a_i, b_r, b_i, Mv[j].x, Mv[j].y, Mv[j].z, Mv[j].w);
        float c0, s0;
        __sincosf(ph[0], &s0, &c0);
        fsh[tid] = c0 * a_r - s0 * a_i;                // f(theta_m)
    }
    __syncthreads();

    // Phase 3a: 28-pt DCT spread over 112 threads (4 partials of 7 terms per j).
    // Exact integer angle reduction: cos(pi*r/56) = -cos(pi*r/56 - pi), r mod 112.
    if (tid < NNODE * 4) {
        int j = tid >> 2;
        int q = tid & 3;
        float s = 0.f;
        int m0 = q * 7;
        #pragma unroll
        for (int m = m0; m < m0 + 7; m++) {
            int r = (j * (2 * m + 1)) % 112;
            float ang = (PI / 56.0f) * (float)r - PI;
            s = fmaf(fsh[m], -__cosf(ang), s);
        }
        psum[tid] = s;
    }
    __syncthreads();

    // Phase 3b: reduce partials -> d_j.
    if (tid < NNODE) {
        float s = ((psum[tid * 4] + psum[tid * 4 + 1]) +
                   (psum[tid * 4 + 2] + psum[tid * 4 + 3])) * (2.0f / (float)NNODE);
        if (tid == 0) s *= 0.5f;
        dsh[tid] = s;
    }
    __syncthreads();

    // Phase 4: even/odd split (exact integer weights), duplicated float2 out.
    if (tid < NHALF) {
        float g = dsh[2 * tid];
        gsh[tid] = make_float2(g, g);
        float h = 0.f, sign = 1.f;
        #pragma unroll 1
        for (int m = tid; m < NHALF; m++) {
            h = fmaf(sign, dsh[2 * m + 1], h);
            sign = -sign;
        }
        if (tid > 0) h *= 2.0f;
        hsh[tid] = make_float2(h, h);
    }
    __syncthreads();

    // Eval: 4 elems/thread, packed f32x2, 4 independent 13-step Clenshaw chains.
    int i = blockIdx.x * blockDim.x + tid;
    if (i >= n4) return;

    float4 xv = x4[i];
    float4 av = a4[i];
    float  b0 = __ldg(bias);

    float y0 = __cosf(2.0f * xv.x), y1 = __cosf(2.0f * xv.y);
    float y2 = __cosf(2.0f * xv.z), y3 = __cosf(2.0f * xv.w);

    u64 neg1 = pack2(-1.f, -1.f);
    u64 yP = pack2(y0, y1), yQ = pack2(y2, y3);
    u64 uP = fma2(add2(yP, yP), yP, neg1);         // u = 2y^2 - 1
    u64 uQ = fma2(add2(yQ, yQ), yQ, neg1);
    u64 tuP = add2(uP, uP), tuQ = add2(uQ, uQ);

    u64 gb1P = 0, gb2P = 0, hb1P = 0, hb2P = 0;
    u64 gb1Q = 0, gb2Q = 0, hb1Q = 0, hb2Q = 0;

    #pragma unroll
    for (int k = NHALF - 1; k >= 1; k--) {
        float2 gt = gsh[k];
        float2 ht = hsh[k];
        u64 gk, hk;
        asm("mov.b64 %0, {%1, %2};" : "=l"(gk) : "f"(gt.x), "f"(gt.y));
        asm("mov.b64 %0, {%1, %2};" : "=l"(hk) : "f"(ht.x), "f"(ht.y));
        u64 ngP = fma2(tuP, gb1P, fma2(neg1, gb2P, gk));
        u64 nhP = fma2(tuP, hb1P, fma2(neg1, hb2P, hk));
        u64 ngQ = fma2(tuQ, gb1Q, fma2(neg1, gb2Q, gk));
        u64 nhQ = fma2(tuQ, hb1Q, fma2(neg1, hb2Q, hk));
        gb2P = gb1P; gb1P = ngP;  hb2P = hb1P; hb1P = nhP;
        gb2Q = gb1Q; gb1Q = ngQ;  hb2Q = hb1Q; hb1Q = nhQ;
    }

    float2 g0t = gsh[0], h0t = hsh[0];
    u64 g0k, h0k;
    asm("mov.b64 %0, {%1, %2};" : "=l"(g0k) : "f"(g0t.x), "f"(g0t.y));
    asm("mov.b64 %0, {%1, %2};" : "=l"(h0k) : "f"(h0t.x), "f"(h0t.y));

    u64 GP = fma2(uP, gb1P, fma2(neg1, gb2P, g0k));
    u64 HP = fma2(uP, hb1P, fma2(neg1, hb2P, h0k));
    u64 GQ = fma2(uQ, gb1Q, fma2(neg1, gb2Q, g0k));
    u64 HQ = fma2(uQ, hb1Q, fma2(neg1, hb2Q, h0k));

    u64 fP = fma2(yP, HP, GP);                     // f = G + y*H
    u64 fQ = fma2(yQ, HQ, GQ);

    u64 aP = pack2(av.x, av.y), aQ = pack2(av.z, av.w);
    u64 bP = pack2(b0, b0);
    u64 oP = fma2(aP, fP, bP);
    u64 oQ = fma2(aQ, fQ, bP);

    float4 o;
    unpack2(oP, o.x, o.y);
    unpack2(oQ, o.z, o.w);
    out4[i] = o;
}

extern "C" void kernel_launch(void* const* d_in, const int* in_sizes, int n_in,
                              void* d_out, int out_size) {
    const float* x    = (const float*)d_in[0];
    const float* p    = (const float*)d_in[1];
    const float* al   = (const float*)d_in[2];
    const float* bias = (const float*)d_in[3];

    int n4 = out_size / 4;                         // 131072
    int threads = 448;                             // 14 warps; 2 CTAs/SM
    int blocks = (n4 + threads - 1) / threads;     // 293
    blocks = ((blocks + 147) / 148) * 148;         // round up: 296 = exactly 2/SM
    if (blocks < (n4 + threads - 1) / threads)     // safety (never true on GB300)
        blocks = (n4 + threads - 1) / threads;
    qsp_fused<<<blocks, threads>>>((const float4*)x, p, (const float4*)al, bias,
                                   (float4*)d_out, n4);
}